// round 1
// baseline (speedup 1.0000x reference)
#include <cuda_runtime.h>
#include <cuda_bf16.h>
#include <math.h>
#include <stdint.h>

// Problem constants
#define TT 256      // T
#define BBATCH 64   // B
#define EE 512      // E (= input dim for ALL layers, since 2H = 512)
#define HH 256      // H
#define G4 1024     // 4H
#define HD2 512     // 2H
#define NTAGS 6
#define TAG_START 4
#define TAG_STOP 5
#define NEGV -1000000.0f

// ---------------- device scratch (static allocations only) ----------------
__device__ float g_x[(size_t)TT * BBATCH * EE];            // layer input / z buffer  (33.5 MB)
__device__ float g_y[(size_t)TT * BBATCH * EE];            // layer output / lstm_out (33.5 MB)
__device__ float g_pre[(size_t)TT * BBATCH * 2048];        // (t,b,[dir0 1024 | dir1 1024]) 134 MB
__device__ float g_h[2 * 2 * HH * BBATCH];                 // [parity][dir][u][b]
__device__ float g_c[2 * HH * BBATCH];                     // [dir][u][b]
__device__ float g_bias[3 * 2 * G4];                       // b_ih + b_hh combined
__device__ float g_wt[(size_t)3 * 2 * 64 * 4096];          // w_hh re-tiled per (layer,dir,uchunk): [k][ul][gate]
__device__ float g_energy[(size_t)TT * BBATCH];            // energy then softmax weights, [t*64+b]
__device__ float g_feats[(size_t)BBATCH * TT * NTAGS];     // [b][t][tag]

// ---------------- tiny utility kernels ----------------
__global__ void zero_out_kernel(float* out) { out[0] = 0.f; }

__global__ void bias_kernel(const float* __restrict__ b_ih, const float* __restrict__ b_hh) {
    int i = blockIdx.x * blockDim.x + threadIdx.x;
    if (i < 3 * 2 * G4) g_bias[i] = b_ih[i] + b_hh[i];
}

__global__ void zero_state_kernel() {
    int i = blockIdx.x * blockDim.x + threadIdx.x;
    if (i < 2 * 2 * HH * BBATCH) g_h[i] = 0.f;
    if (i < 2 * HH * BBATCH) g_c[i] = 0.f;
}

// Re-tile w_hh (3,2,1024,256) into g_wt[(l,d,uc)][k*16 + ul*4 + g]
__global__ void wt_kernel(const float* __restrict__ whh) {
    size_t i = (size_t)blockIdx.x * blockDim.x + threadIdx.x;
    const size_t n = (size_t)3 * 2 * 64 * 4096;
    if (i >= n) return;
    int g  = i & 3;
    int ul = (i >> 2) & 3;
    int k  = (i >> 4) & 255;
    int uc = (i >> 12) & 63;
    int ld = (int)(i >> 18);   // l*2 + d, 0..5
    g_wt[i] = whh[((size_t)ld * G4 + g * 256 + uc * 4 + ul) * HH + k];
}

// gather embeddings -> g_x[t][b][e]
__global__ void embed_kernel(const int* __restrict__ sent, const float* __restrict__ emb) {
    size_t i = (size_t)blockIdx.x * blockDim.x + threadIdx.x;
    const size_t n = (size_t)TT * BBATCH * EE;
    if (i >= n) return;
    int e = i & (EE - 1);
    size_t r = i >> 9;
    int b = r & (BBATCH - 1);
    int t = (int)(r >> 6);
    g_x[i] = emb[(size_t)sent[b * TT + t] * EE + e];
}

// ---------------- fp32 SGEMM: C[M,N] = A[M,K] @ W[N,K]^T + bias[N] ----------------
// 128x128 tile, 256 threads, 8x8 micro-tile, K-tile 8. M,N multiples of 128, K multiple of 8.
__global__ __launch_bounds__(256) void sgemm_bias_kernel(
    const float* __restrict__ A, const float* __restrict__ W,
    const float* __restrict__ bias, float* __restrict__ C,
    int M, int N, int K)
{
    __shared__ float As[8][128];
    __shared__ float Bs[8][128];
    const int tid = threadIdx.x;
    const int bm = blockIdx.y * 128, bn = blockIdx.x * 128;
    const int lr = tid >> 1;
    const int lk = (tid & 1) * 4;
    const int tx = tid & 15, ty = tid >> 4;

    float acc[8][8];
#pragma unroll
    for (int i = 0; i < 8; i++)
#pragma unroll
        for (int j = 0; j < 8; j++) acc[i][j] = 0.f;

    const float* Aptr = A + (size_t)(bm + lr) * K + lk;
    const float* Wptr = W + (size_t)(bn + lr) * K + lk;

    for (int k0 = 0; k0 < K; k0 += 8) {
        float4 a4 = *(const float4*)(Aptr + k0);
        float4 b4 = *(const float4*)(Wptr + k0);
        As[lk + 0][lr] = a4.x; As[lk + 1][lr] = a4.y; As[lk + 2][lr] = a4.z; As[lk + 3][lr] = a4.w;
        Bs[lk + 0][lr] = b4.x; Bs[lk + 1][lr] = b4.y; Bs[lk + 2][lr] = b4.z; Bs[lk + 3][lr] = b4.w;
        __syncthreads();
#pragma unroll
        for (int kk = 0; kk < 8; kk++) {
            float ar[8], br[8];
            *(float4*)(ar)     = *(const float4*)&As[kk][ty * 8];
            *(float4*)(ar + 4) = *(const float4*)&As[kk][ty * 8 + 4];
            *(float4*)(br)     = *(const float4*)&Bs[kk][tx * 8];
            *(float4*)(br + 4) = *(const float4*)&Bs[kk][tx * 8 + 4];
#pragma unroll
            for (int i = 0; i < 8; i++)
#pragma unroll
                for (int j = 0; j < 8; j++) acc[i][j] += ar[i] * br[j];
        }
        __syncthreads();
    }
    float bb[8];
#pragma unroll
    for (int j = 0; j < 8; j++) bb[j] = bias[bn + tx * 8 + j];
#pragma unroll
    for (int i = 0; i < 8; i++) {
        size_t row = (size_t)(bm + ty * 8 + i);
        float4 o0, o1;
        o0.x = acc[i][0] + bb[0]; o0.y = acc[i][1] + bb[1];
        o0.z = acc[i][2] + bb[2]; o0.w = acc[i][3] + bb[3];
        o1.x = acc[i][4] + bb[4]; o1.y = acc[i][5] + bb[5];
        o1.z = acc[i][6] + bb[6]; o1.w = acc[i][7] + bb[7];
        *(float4*)(C + row * N + bn + tx * 8)     = o0;
        *(float4*)(C + row * N + bn + tx * 8 + 4) = o1;
    }
}

// ---------------- one LSTM time step (both directions), grid=128, block=128 ----------------
// block: d = bi>>6, uchunk (4 hidden units) = bi&63. thread: ul = tid&3, batch pair b0 = (tid>>2)*2.
// smem: hs[256][64] (h state, k-major) + ws[256][16] ([k][ul][gate], pre-tiled) = 80 KB dynamic.
__global__ __launch_bounds__(128) void lstm_step_kernel(
    const float* __restrict__ wt_l,  // g_wt + l*2*64*4096
    int s, float* __restrict__ out)
{
    extern __shared__ float sm[];
    float* hs = sm;             // 16384 floats
    float* ws = sm + 16384;     // 4096 floats
    const int d  = blockIdx.x >> 6;
    const int uc = blockIdx.x & 63;
    const int u0 = uc * 4;
    const int tid = threadIdx.x;
    const int rp = s & 1, wp = rp ^ 1;
    const int tt = d ? (TT - 1 - s) : s;

    const float4* hsrc4 = (const float4*)(g_h + (size_t)(rp * 2 + d) * (HH * BBATCH));
    float4* hs4 = (float4*)hs;
    for (int i = tid; i < 4096; i += 128) hs4[i] = hsrc4[i];

    const float4* wsrc4 = (const float4*)(wt_l + ((size_t)d * 64 + uc) * 4096);
    float4* ws4 = (float4*)ws;
    for (int i = tid; i < 1024; i += 128) ws4[i] = wsrc4[i];

    const int ul = tid & 3;
    const int b0 = (tid >> 2) * 2;

    // prefetch pre-activation (xW + biases)
    const float* prow = g_pre + (size_t)tt * BBATCH * 2048 + (size_t)d * G4;
    float p0[4], p1[4];
#pragma unroll
    for (int g = 0; g < 4; g++) {
        p0[g] = prow[(size_t)b0 * 2048 + g * 256 + u0 + ul];
        p1[g] = prow[(size_t)(b0 + 1) * 2048 + g * 256 + u0 + ul];
    }
    __syncthreads();

    float a00 = 0, a01 = 0, a02 = 0, a03 = 0;
    float a10 = 0, a11 = 0, a12 = 0, a13 = 0;
#pragma unroll 8
    for (int k = 0; k < 256; k++) {
        float2 hv = *(const float2*)&hs[k * 64 + b0];
        float4 wv = *(const float4*)&ws[k * 16 + ul * 4];
        a00 += hv.x * wv.x; a01 += hv.x * wv.y; a02 += hv.x * wv.z; a03 += hv.x * wv.w;
        a10 += hv.y * wv.x; a11 += hv.y * wv.y; a12 += hv.y * wv.z; a13 += hv.y * wv.w;
    }
    const int u = u0 + ul;
#pragma unroll
    for (int bb = 0; bb < 2; bb++) {
        int b = b0 + bb;
        float gi = (bb ? p1[0] : p0[0]) + (bb ? a10 : a00);
        float gf = (bb ? p1[1] : p0[1]) + (bb ? a11 : a01);
        float gg = (bb ? p1[2] : p0[2]) + (bb ? a12 : a02);
        float go = (bb ? p1[3] : p0[3]) + (bb ? a13 : a03);
        float iv = 1.f / (1.f + expf(-gi));
        float fv = 1.f / (1.f + expf(-gf));
        float gv = tanhf(gg);
        float ov = 1.f / (1.f + expf(-go));
        size_t ci = (size_t)d * (HH * BBATCH) + u * 64 + b;
        float c = fv * g_c[ci] + iv * gv;
        g_c[ci] = c;
        float h = ov * tanhf(c);
        g_h[(size_t)(wp * 2 + d) * (HH * BBATCH) + u * 64 + b] = h;
        out[(size_t)tt * BBATCH * HD2 + (size_t)b * HD2 + d * HH + u] = h;
    }
}

// ---------------- attention ----------------
// energy[r] = sum_k tanh(z[r][k]) * aw2[k] + ab2   (z already has ab1 via GEMM bias)
__global__ __launch_bounds__(256) void energy_kernel(const float* __restrict__ z,
                                                     const float* __restrict__ aw2,
                                                     const float* __restrict__ ab2)
{
    int w = threadIdx.x >> 5, lane = threadIdx.x & 31;
    int r = blockIdx.x * 8 + w;
    const float* zr = z + (size_t)r * 512;
    float acc = 0.f;
#pragma unroll
    for (int j = 0; j < 16; j++) {
        int k = lane + j * 32;
        acc += tanhf(zr[k]) * aw2[k];
    }
#pragma unroll
    for (int o = 16; o > 0; o >>= 1) acc += __shfl_down_sync(0xffffffffu, acc, o);
    if (lane == 0) g_energy[r] = acc + ab2[0];
}

// softmax over t (per batch b); in-place on g_energy (layout [t*64+b])
__global__ __launch_bounds__(256) void softmax_kernel() {
    __shared__ float red[256];
    int b = blockIdx.x, t = threadIdx.x;
    float e = g_energy[t * 64 + b];
    red[t] = e;
    __syncthreads();
    for (int s = 128; s > 0; s >>= 1) {
        if (t < s) red[t] = fmaxf(red[t], red[t + s]);
        __syncthreads();
    }
    float m = red[0];
    __syncthreads();
    float p = expf(e - m);
    red[t] = p;
    __syncthreads();
    for (int s = 128; s > 0; s >>= 1) {
        if (t < s) red[t] += red[t + s];
        __syncthreads();
    }
    g_energy[t * 64 + b] = p / red[0];
}

// feats[b][t][i] = (1 + weight[r]) * (y_row . hw_i) + hb[i]
__global__ __launch_bounds__(256) void feats_kernel(const float* __restrict__ y,
                                                    const float* __restrict__ hw,
                                                    const float* __restrict__ hb)
{
    int w = threadIdx.x >> 5, lane = threadIdx.x & 31;
    int r = blockIdx.x * 8 + w;
    const float* yr = y + (size_t)r * 512;
    float acc[NTAGS];
#pragma unroll
    for (int i = 0; i < NTAGS; i++) acc[i] = 0.f;
#pragma unroll
    for (int j = 0; j < 16; j++) {
        int k = lane + j * 32;
        float v = yr[k];
#pragma unroll
        for (int i = 0; i < NTAGS; i++) acc[i] += v * hw[i * 512 + k];
    }
#pragma unroll
    for (int i = 0; i < NTAGS; i++)
#pragma unroll
        for (int o = 16; o > 0; o >>= 1) acc[i] += __shfl_down_sync(0xffffffffu, acc[i], o);
    if (lane == 0) {
        float wt = 1.f + g_energy[r];
        int b = r & 63, t = r >> 6;
#pragma unroll
        for (int i = 0; i < NTAGS; i++)
            g_feats[((size_t)b * TT + t) * NTAGS + i] = wt * acc[i] + hb[i];
    }
}

// ---------------- CRF: forward score + gold score, 1 warp per batch ----------------
__global__ __launch_bounds__(32) void crf_kernel(const int* __restrict__ tags,
                                                 const float* __restrict__ mask,
                                                 const float* __restrict__ trans,
                                                 float* __restrict__ out)
{
    __shared__ float tr[36];
    int b = blockIdx.x, lid = threadIdx.x;
    for (int i = lid; i < 36; i += 32) tr[i] = trans[i];
    __syncwarp();

    const int ii = lid % NTAGS;              // lanes >=6 mirror lanes 0..5 (harmless dup)
    const float* fb = g_feats + (size_t)b * TT * NTAGS;
    const float* mb = mask + (size_t)b * TT;

    float fv = (ii == TAG_START) ? 0.f : NEGV;
    for (int t = 0; t < TT; t++) {
        float fj[NTAGS];
#pragma unroll
        for (int j = 0; j < NTAGS; j++) fj[j] = __shfl_sync(0xffffffffu, fv, j);
        float v[NTAGS];
        float m = -3.4e38f;
#pragma unroll
        for (int j = 0; j < NTAGS; j++) {
            v[j] = fj[j] + tr[ii * NTAGS + j];
            m = fmaxf(m, v[j]);
        }
        float ssum = 0.f;
#pragma unroll
        for (int j = 0; j < NTAGS; j++) ssum += expf(v[j] - m);
        float nxt = m + logf(ssum) + fb[t * NTAGS + ii];
        fv = (mb[t] > 0.f) ? nxt : fv;
    }
    // forward score = logsumexp_i(fv_i + trans[STOP][i])
    float sv = fv + tr[TAG_STOP * NTAGS + ii];
    float gvals[NTAGS];
#pragma unroll
    for (int j = 0; j < NTAGS; j++) gvals[j] = __shfl_sync(0xffffffffu, sv, j);
    float m2 = -3.4e38f;
#pragma unroll
    for (int j = 0; j < NTAGS; j++) m2 = fmaxf(m2, gvals[j]);
    float s2 = 0.f;
#pragma unroll
    for (int j = 0; j < NTAGS; j++) s2 += expf(gvals[j] - m2);
    float fwd = m2 + logf(s2);

    // gold score
    float gold = 0.f, msum = 0.f;
    for (int t = lid; t < TT; t += 32) {
        int cur = tags[b * TT + t];
        int prev = t ? tags[b * TT + t - 1] : TAG_START;
        float mm = mb[t];
        gold += (fb[t * NTAGS + cur] + tr[cur * NTAGS + prev]) * mm;
        msum += mm;
    }
#pragma unroll
    for (int o = 16; o > 0; o >>= 1) {
        gold += __shfl_down_sync(0xffffffffu, gold, o);
        msum += __shfl_down_sync(0xffffffffu, msum, o);
    }
    if (lid == 0) {
        int sl = (int)(msum + 0.5f);
        int last = (sl > 0) ? tags[b * TT + sl - 1] : TAG_START;
        gold += tr[TAG_STOP * NTAGS + last];
        atomicAdd(out, (fwd - gold) * (1.f / 64.f));
    }
}

// ---------------- launch ----------------
extern "C" void kernel_launch(void* const* d_in, const int* in_sizes, int n_in,
                              void* d_out, int out_size)
{
    const int*   sentences = (const int*)d_in[0];
    const int*   tags      = (const int*)d_in[1];
    const float* mask      = (const float*)d_in[2];
    const float* embed     = (const float*)d_in[3];
    const float* w_ih      = (const float*)d_in[4];
    const float* w_hh      = (const float*)d_in[5];
    const float* b_ih      = (const float*)d_in[6];
    const float* b_hh      = (const float*)d_in[7];
    const float* aw1       = (const float*)d_in[8];
    const float* ab1       = (const float*)d_in[9];
    const float* aw2       = (const float*)d_in[10];
    const float* ab2       = (const float*)d_in[11];
    const float* hw        = (const float*)d_in[12];
    const float* hb        = (const float*)d_in[13];
    const float* trans     = (const float*)d_in[14];
    float* out = (float*)d_out;

    const int STEP_SMEM = (16384 + 4096) * 4;  // 80 KB
    cudaFuncSetAttribute(lstm_step_kernel, cudaFuncAttributeMaxDynamicSharedMemorySize, STEP_SMEM);

    zero_out_kernel<<<1, 1>>>(out);
    bias_kernel<<<24, 256>>>(b_ih, b_hh);
    wt_kernel<<<6144, 256>>>(w_hh);
    embed_kernel<<<32768, 256>>>(sentences, embed);

    // resolve device-global addresses on host
    float *px, *py, *ppre, *pbias, *pwt, *penergy;
    cudaGetSymbolAddress((void**)&px, g_x);
    cudaGetSymbolAddress((void**)&py, g_y);
    cudaGetSymbolAddress((void**)&ppre, g_pre);
    cudaGetSymbolAddress((void**)&pbias, g_bias);
    cudaGetSymbolAddress((void**)&pwt, g_wt);
    cudaGetSymbolAddress((void**)&penergy, g_energy);

    const int M = TT * BBATCH;  // 16384
    float* lin = px;
    float* lout = py;
    for (int l = 0; l < 3; l++) {
        zero_state_kernel<<<384, 256>>>();
        dim3 g1(2048 / 128, M / 128);
        sgemm_bias_kernel<<<g1, 256>>>(lin, w_ih + (size_t)l * 2 * G4 * EE,
                                       pbias + l * 2048, ppre, M, 2048, EE);
        const float* wtl = pwt + (size_t)l * 2 * 64 * 4096;
        for (int s = 0; s < TT; s++)
            lstm_step_kernel<<<128, 128, STEP_SMEM>>>(wtl, s, lout);
        float* tmp = lin; lin = lout; lout = tmp;
    }
    // after 3 layers: lstm_out lives in g_y (lin == py now)
    float* lstm_out = lin;   // == py
    float* zbuf = lout;      // == px

    dim3 g2(512 / 128, M / 128);
    sgemm_bias_kernel<<<g2, 256>>>(lstm_out, aw1, ab1, zbuf, M, 512, EE);
    energy_kernel<<<M / 8, 256>>>(zbuf, aw2, ab2);
    softmax_kernel<<<BBATCH, 256>>>();
    feats_kernel<<<M / 8, 256>>>(lstm_out, hw, hb);
    crf_kernel<<<BBATCH, 32>>>(tags, mask, trans, out);
}

// round 2
// speedup vs baseline: 1.1427x; 1.1427x over previous
#include <cuda_runtime.h>
#include <cuda_bf16.h>
#include <math.h>
#include <stdint.h>

// Problem constants
#define TT 256      // T
#define BBATCH 64   // B
#define EE 512      // E (= input dim for ALL layers, since 2H = 512)
#define HH 256      // H
#define G4 1024     // 4H
#define HD2 512     // 2H
#define NTAGS 6
#define TAG_START 4
#define TAG_STOP 5
#define NEGV -1000000.0f

// ---------------- device scratch (static allocations only) ----------------
__device__ float g_x[(size_t)TT * BBATCH * EE];            // layer input / z buffer  (33.5 MB)
__device__ float g_y[(size_t)TT * BBATCH * EE];            // layer output / lstm_out (33.5 MB)
__device__ float g_pre[(size_t)TT * BBATCH * 2048];        // (t,b,[dir0 1024 | dir1 1024]) 134 MB
__device__ float g_h[2 * 2 * HH * BBATCH];                 // [parity][dir][u][b]
__device__ float g_bias[3 * 2 * G4];                       // b_ih + b_hh combined
__device__ float g_wt[(size_t)3 * 2 * 64 * 4096];          // w_hh re-tiled per (layer,dir,uchunk): [k][ul][gate]
__device__ float g_energy[(size_t)TT * BBATCH];            // energy then softmax weights, [t*64+b]
__device__ float g_feats[(size_t)BBATCH * TT * NTAGS];     // [b][t][tag]
__device__ unsigned int g_bar[2];                          // per-direction step barrier counters

// ---------------- tiny utility kernels ----------------
__global__ void zero_out_kernel(float* out) { out[0] = 0.f; }

__global__ void bias_kernel(const float* __restrict__ b_ih, const float* __restrict__ b_hh) {
    int i = blockIdx.x * blockDim.x + threadIdx.x;
    if (i < 3 * 2 * G4) g_bias[i] = b_ih[i] + b_hh[i];
}

__global__ void zero_state_kernel() {
    int i = blockIdx.x * blockDim.x + threadIdx.x;
    if (i < 2 * 2 * HH * BBATCH) g_h[i] = 0.f;
    if (i < 2) g_bar[i] = 0u;
}

// Re-tile w_hh (3,2,1024,256) into g_wt[(l,d,uc)][k*16 + ul*4 + g]
__global__ void wt_kernel(const float* __restrict__ whh) {
    size_t i = (size_t)blockIdx.x * blockDim.x + threadIdx.x;
    const size_t n = (size_t)3 * 2 * 64 * 4096;
    if (i >= n) return;
    int g  = i & 3;
    int ul = (i >> 2) & 3;
    int k  = (i >> 4) & 255;
    int uc = (i >> 12) & 63;
    int ld = (int)(i >> 18);   // l*2 + d, 0..5
    g_wt[i] = whh[((size_t)ld * G4 + g * 256 + uc * 4 + ul) * HH + k];
}

// gather embeddings -> g_x[t][b][e]
__global__ void embed_kernel(const int* __restrict__ sent, const float* __restrict__ emb) {
    size_t i = (size_t)blockIdx.x * blockDim.x + threadIdx.x;
    const size_t n = (size_t)TT * BBATCH * EE;
    if (i >= n) return;
    int e = i & (EE - 1);
    size_t r = i >> 9;
    int b = r & (BBATCH - 1);
    int t = (int)(r >> 6);
    g_x[i] = emb[(size_t)sent[b * TT + t] * EE + e];
}

// ---------------- fp32 SGEMM: C[M,N] = A[M,K] @ W[N,K]^T + bias[N] ----------------
// 128x128 tile, 256 threads, 8x8 micro-tile, K-tile 8. M,N multiples of 128, K multiple of 8.
__global__ __launch_bounds__(256) void sgemm_bias_kernel(
    const float* __restrict__ A, const float* __restrict__ W,
    const float* __restrict__ bias, float* __restrict__ C,
    int M, int N, int K)
{
    __shared__ float As[8][128];
    __shared__ float Bs[8][128];
    const int tid = threadIdx.x;
    const int bm = blockIdx.y * 128, bn = blockIdx.x * 128;
    const int lr = tid >> 1;
    const int lk = (tid & 1) * 4;
    const int tx = tid & 15, ty = tid >> 4;

    float acc[8][8];
#pragma unroll
    for (int i = 0; i < 8; i++)
#pragma unroll
        for (int j = 0; j < 8; j++) acc[i][j] = 0.f;

    const float* Aptr = A + (size_t)(bm + lr) * K + lk;
    const float* Wptr = W + (size_t)(bn + lr) * K + lk;

    for (int k0 = 0; k0 < K; k0 += 8) {
        float4 a4 = *(const float4*)(Aptr + k0);
        float4 b4 = *(const float4*)(Wptr + k0);
        As[lk + 0][lr] = a4.x; As[lk + 1][lr] = a4.y; As[lk + 2][lr] = a4.z; As[lk + 3][lr] = a4.w;
        Bs[lk + 0][lr] = b4.x; Bs[lk + 1][lr] = b4.y; Bs[lk + 2][lr] = b4.z; Bs[lk + 3][lr] = b4.w;
        __syncthreads();
#pragma unroll
        for (int kk = 0; kk < 8; kk++) {
            float ar[8], br[8];
            *(float4*)(ar)     = *(const float4*)&As[kk][ty * 8];
            *(float4*)(ar + 4) = *(const float4*)&As[kk][ty * 8 + 4];
            *(float4*)(br)     = *(const float4*)&Bs[kk][tx * 8];
            *(float4*)(br + 4) = *(const float4*)&Bs[kk][tx * 8 + 4];
#pragma unroll
            for (int i = 0; i < 8; i++)
#pragma unroll
                for (int j = 0; j < 8; j++) acc[i][j] += ar[i] * br[j];
        }
        __syncthreads();
    }
    float bb[8];
#pragma unroll
    for (int j = 0; j < 8; j++) bb[j] = bias[bn + tx * 8 + j];
#pragma unroll
    for (int i = 0; i < 8; i++) {
        size_t row = (size_t)(bm + ty * 8 + i);
        float4 o0, o1;
        o0.x = acc[i][0] + bb[0]; o0.y = acc[i][1] + bb[1];
        o0.z = acc[i][2] + bb[2]; o0.w = acc[i][3] + bb[3];
        o1.x = acc[i][4] + bb[4]; o1.y = acc[i][5] + bb[5];
        o1.z = acc[i][6] + bb[6]; o1.w = acc[i][7] + bb[7];
        *(float4*)(C + row * N + bn + tx * 8)     = o0;
        *(float4*)(C + row * N + bn + tx * 8 + 4) = o1;
    }
}

// ---------------- persistent LSTM layer kernel ----------------
// One launch runs ALL 256 time steps of one layer, both directions.
// grid=128 (d = bi>>6, uchunk = bi&63), block=128. All blocks co-resident
// (128 <= 148 SMs), synchronized per step with a per-direction counter barrier.
// W_hh tile (16 KB) loaded into smem ONCE; c-state lives in registers.
// h-state exchanged through L2: __ldcg reads (L1 incoherent across SMs).
__device__ __forceinline__ unsigned int ld_cg_u32(const unsigned int* p) {
    unsigned int v;
    asm volatile("ld.global.cg.u32 %0, [%1];" : "=r"(v) : "l"(p));
    return v;
}

__global__ __launch_bounds__(128) void lstm_layer_kernel(
    const float* __restrict__ wt_l,   // g_wt + l*2*64*4096
    const float* __restrict__ pre,    // g_pre
    float* __restrict__ out)
{
    extern __shared__ float sm[];
    float* hs = sm;             // 16384 floats
    float* ws = sm + 16384;     // 4096 floats
    const int d  = blockIdx.x >> 6;
    const int uc = blockIdx.x & 63;
    const int u0 = uc * 4;
    const int tid = threadIdx.x;
    const int ul = tid & 3;
    const int b0 = (tid >> 2) * 2;
    const int u  = u0 + ul;

    // load W_hh tile once for the whole layer
    const float4* wsrc4 = (const float4*)(wt_l + ((size_t)d * 64 + uc) * 4096);
    float4* ws4 = (float4*)ws;
    for (int i = tid; i < 1024; i += 128) ws4[i] = wsrc4[i];

    float c0 = 0.f, c1 = 0.f;                 // c-state in registers
    unsigned int* bar = &g_bar[d];
    float4* hs4 = (float4*)hs;

    for (int s = 0; s < TT; s++) {
        const int tt = d ? (TT - 1 - s) : s;
        const int rp = s & 1, wp = rp ^ 1;

        // prefetch pre-activation (independent of the barrier)
        const float* prow = pre + (size_t)tt * BBATCH * 2048 + (size_t)d * G4;
        float p0[4], p1[4];
#pragma unroll
        for (int g = 0; g < 4; g++) {
            p0[g] = __ldg(&prow[(size_t)b0 * 2048 + g * 256 + u]);
            p1[g] = __ldg(&prow[(size_t)(b0 + 1) * 2048 + g * 256 + u]);
        }

        // wait: all 64 blocks of this direction finished step s-1
        if (s) {
            if (tid == 0) {
                const unsigned int target = 64u * (unsigned int)s;
                while (ld_cg_u32(bar) < target) __nanosleep(32);
            }
            __syncthreads();
        }

        // load h (parity rp) for this direction into smem, via L2
        const float4* hsrc4 = (const float4*)(g_h + (size_t)(rp * 2 + d) * (HH * BBATCH));
#pragma unroll
        for (int i = tid; i < 4096; i += 128) hs4[i] = __ldcg(hsrc4 + i);
        __syncthreads();

        float a00 = 0, a01 = 0, a02 = 0, a03 = 0;
        float a10 = 0, a11 = 0, a12 = 0, a13 = 0;
#pragma unroll 8
        for (int k = 0; k < 256; k++) {
            float2 hv = *(const float2*)&hs[k * 64 + b0];
            float4 wv = *(const float4*)&ws[k * 16 + ul * 4];
            a00 += hv.x * wv.x; a01 += hv.x * wv.y; a02 += hv.x * wv.z; a03 += hv.x * wv.w;
            a10 += hv.y * wv.x; a11 += hv.y * wv.y; a12 += hv.y * wv.z; a13 += hv.y * wv.w;
        }

#pragma unroll
        for (int bb = 0; bb < 2; bb++) {
            int b = b0 + bb;
            float gi = (bb ? p1[0] : p0[0]) + (bb ? a10 : a00);
            float gf = (bb ? p1[1] : p0[1]) + (bb ? a11 : a01);
            float gg = (bb ? p1[2] : p0[2]) + (bb ? a12 : a02);
            float go = (bb ? p1[3] : p0[3]) + (bb ? a13 : a03);
            float iv = 1.f / (1.f + expf(-gi));
            float fv = 1.f / (1.f + expf(-gf));
            float gv = tanhf(gg);
            float ov = 1.f / (1.f + expf(-go));
            float cprev = bb ? c1 : c0;
            float c = fv * cprev + iv * gv;
            if (bb) c1 = c; else c0 = c;
            float h = ov * tanhf(c);
            g_h[(size_t)(wp * 2 + d) * (HH * BBATCH) + u * 64 + b] = h;
            out[(size_t)tt * BBATCH * HD2 + (size_t)b * HD2 + d * HH + u] = h;
        }

        // release: make h visible in L2, then signal
        __syncthreads();
        if (tid == 0) {
            __threadfence();
            atomicAdd(bar, 1u);
        }
    }
}

// ---------------- attention ----------------
__global__ __launch_bounds__(256) void energy_kernel(const float* __restrict__ z,
                                                     const float* __restrict__ aw2,
                                                     const float* __restrict__ ab2)
{
    int w = threadIdx.x >> 5, lane = threadIdx.x & 31;
    int r = blockIdx.x * 8 + w;
    const float* zr = z + (size_t)r * 512;
    float acc = 0.f;
#pragma unroll
    for (int j = 0; j < 16; j++) {
        int k = lane + j * 32;
        acc += tanhf(zr[k]) * aw2[k];
    }
#pragma unroll
    for (int o = 16; o > 0; o >>= 1) acc += __shfl_down_sync(0xffffffffu, acc, o);
    if (lane == 0) g_energy[r] = acc + ab2[0];
}

__global__ __launch_bounds__(256) void softmax_kernel() {
    __shared__ float red[256];
    int b = blockIdx.x, t = threadIdx.x;
    float e = g_energy[t * 64 + b];
    red[t] = e;
    __syncthreads();
    for (int s = 128; s > 0; s >>= 1) {
        if (t < s) red[t] = fmaxf(red[t], red[t + s]);
        __syncthreads();
    }
    float m = red[0];
    __syncthreads();
    float p = expf(e - m);
    red[t] = p;
    __syncthreads();
    for (int s = 128; s > 0; s >>= 1) {
        if (t < s) red[t] += red[t + s];
        __syncthreads();
    }
    g_energy[t * 64 + b] = p / red[0];
}

__global__ __launch_bounds__(256) void feats_kernel(const float* __restrict__ y,
                                                    const float* __restrict__ hw,
                                                    const float* __restrict__ hb)
{
    int w = threadIdx.x >> 5, lane = threadIdx.x & 31;
    int r = blockIdx.x * 8 + w;
    const float* yr = y + (size_t)r * 512;
    float acc[NTAGS];
#pragma unroll
    for (int i = 0; i < NTAGS; i++) acc[i] = 0.f;
#pragma unroll
    for (int j = 0; j < 16; j++) {
        int k = lane + j * 32;
        float v = yr[k];
#pragma unroll
        for (int i = 0; i < NTAGS; i++) acc[i] += v * hw[i * 512 + k];
    }
#pragma unroll
    for (int i = 0; i < NTAGS; i++)
#pragma unroll
        for (int o = 16; o > 0; o >>= 1) acc[i] += __shfl_down_sync(0xffffffffu, acc[i], o);
    if (lane == 0) {
        float wt = 1.f + g_energy[r];
        int b = r & 63, t = r >> 6;
#pragma unroll
        for (int i = 0; i < NTAGS; i++)
            g_feats[((size_t)b * TT + t) * NTAGS + i] = wt * acc[i] + hb[i];
    }
}

// ---------------- CRF ----------------
__global__ __launch_bounds__(32) void crf_kernel(const int* __restrict__ tags,
                                                 const float* __restrict__ mask,
                                                 const float* __restrict__ trans,
                                                 float* __restrict__ out)
{
    __shared__ float tr[36];
    int b = blockIdx.x, lid = threadIdx.x;
    for (int i = lid; i < 36; i += 32) tr[i] = trans[i];
    __syncwarp();

    const int ii = lid % NTAGS;
    const float* fb = g_feats + (size_t)b * TT * NTAGS;
    const float* mb = mask + (size_t)b * TT;

    float fv = (ii == TAG_START) ? 0.f : NEGV;
    for (int t = 0; t < TT; t++) {
        float fj[NTAGS];
#pragma unroll
        for (int j = 0; j < NTAGS; j++) fj[j] = __shfl_sync(0xffffffffu, fv, j);
        float v[NTAGS];
        float m = -3.4e38f;
#pragma unroll
        for (int j = 0; j < NTAGS; j++) {
            v[j] = fj[j] + tr[ii * NTAGS + j];
            m = fmaxf(m, v[j]);
        }
        float ssum = 0.f;
#pragma unroll
        for (int j = 0; j < NTAGS; j++) ssum += expf(v[j] - m);
        float nxt = m + logf(ssum) + fb[t * NTAGS + ii];
        fv = (mb[t] > 0.f) ? nxt : fv;
    }
    float sv = fv + tr[TAG_STOP * NTAGS + ii];
    float gvals[NTAGS];
#pragma unroll
    for (int j = 0; j < NTAGS; j++) gvals[j] = __shfl_sync(0xffffffffu, sv, j);
    float m2 = -3.4e38f;
#pragma unroll
    for (int j = 0; j < NTAGS; j++) m2 = fmaxf(m2, gvals[j]);
    float s2 = 0.f;
#pragma unroll
    for (int j = 0; j < NTAGS; j++) s2 += expf(gvals[j] - m2);
    float fwd = m2 + logf(s2);

    float gold = 0.f, msum = 0.f;
    for (int t = lid; t < TT; t += 32) {
        int cur = tags[b * TT + t];
        int prev = t ? tags[b * TT + t - 1] : TAG_START;
        float mm = mb[t];
        gold += (fb[t * NTAGS + cur] + tr[cur * NTAGS + prev]) * mm;
        msum += mm;
    }
#pragma unroll
    for (int o = 16; o > 0; o >>= 1) {
        gold += __shfl_down_sync(0xffffffffu, gold, o);
        msum += __shfl_down_sync(0xffffffffu, msum, o);
    }
    if (lid == 0) {
        int sl = (int)(msum + 0.5f);
        int last = (sl > 0) ? tags[b * TT + sl - 1] : TAG_START;
        gold += tr[TAG_STOP * NTAGS + last];
        atomicAdd(out, (fwd - gold) * (1.f / 64.f));
    }
}

// ---------------- launch ----------------
extern "C" void kernel_launch(void* const* d_in, const int* in_sizes, int n_in,
                              void* d_out, int out_size)
{
    const int*   sentences = (const int*)d_in[0];
    const int*   tags      = (const int*)d_in[1];
    const float* mask      = (const float*)d_in[2];
    const float* embed     = (const float*)d_in[3];
    const float* w_ih      = (const float*)d_in[4];
    const float* w_hh      = (const float*)d_in[5];
    const float* b_ih      = (const float*)d_in[6];
    const float* b_hh      = (const float*)d_in[7];
    const float* aw1       = (const float*)d_in[8];
    const float* ab1       = (const float*)d_in[9];
    const float* aw2       = (const float*)d_in[10];
    const float* ab2       = (const float*)d_in[11];
    const float* hw        = (const float*)d_in[12];
    const float* hb        = (const float*)d_in[13];
    const float* trans     = (const float*)d_in[14];
    float* out = (float*)d_out;

    const int STEP_SMEM = (16384 + 4096) * 4;  // 80 KB
    cudaFuncSetAttribute(lstm_layer_kernel, cudaFuncAttributeMaxDynamicSharedMemorySize, STEP_SMEM);

    zero_out_kernel<<<1, 1>>>(out);
    bias_kernel<<<24, 256>>>(b_ih, b_hh);
    wt_kernel<<<6144, 256>>>(w_hh);
    embed_kernel<<<32768, 256>>>(sentences, embed);

    float *px, *py, *ppre, *pbias, *pwt;
    cudaGetSymbolAddress((void**)&px, g_x);
    cudaGetSymbolAddress((void**)&py, g_y);
    cudaGetSymbolAddress((void**)&ppre, g_pre);
    cudaGetSymbolAddress((void**)&pbias, g_bias);
    cudaGetSymbolAddress((void**)&pwt, g_wt);

    const int M = TT * BBATCH;  // 16384
    float* lin = px;
    float* lout = py;
    for (int l = 0; l < 3; l++) {
        zero_state_kernel<<<128, 256>>>();
        dim3 g1(2048 / 128, M / 128);
        sgemm_bias_kernel<<<g1, 256>>>(lin, w_ih + (size_t)l * 2 * G4 * EE,
                                       pbias + l * 2048, ppre, M, 2048, EE);
        const float* wtl = pwt + (size_t)l * 2 * 64 * 4096;
        lstm_layer_kernel<<<128, 128, STEP_SMEM>>>(wtl, ppre, lout);
        float* tmp = lin; lin = lout; lout = tmp;
    }
    float* lstm_out = lin;   // == py
    float* zbuf = lout;      // == px

    dim3 g2(512 / 128, M / 128);
    sgemm_bias_kernel<<<g2, 256>>>(lstm_out, aw1, ab1, zbuf, M, 512, EE);
    energy_kernel<<<M / 8, 256>>>(zbuf, aw2, ab2);
    softmax_kernel<<<BBATCH, 256>>>();
    feats_kernel<<<M / 8, 256>>>(lstm_out, hw, hb);
    crf_kernel<<<BBATCH, 32>>>(tags, mask, trans, out);
}